// round 4
// baseline (speedup 1.0000x reference)
#include <cuda_runtime.h>
#include <cstdint>
#include <cstddef>

#define BATCH 32
#define SEQ 2048
#define DA 32
#define HID 128
#define DS 64
#define NTOK (BATCH * SEQ)       /* 65536 */
#define TRANS_N (DS * DS)        /* 4096  */

/* Scratch: __device__ globals (no allocation allowed). */
__device__ float g_h1[(size_t)NTOK * HID];         /* 32 MB  */
__device__ float g_trans[(size_t)NTOK * TRANS_N];  /* 1 GiB  */

/* ------------------------------------------------------------------ */
/* Kernel A: h1 = relu(relu(a@w0+b0)@w1 + b1) for all 65536 tokens.    */
/* 64 tokens per block, 256 threads.                                   */
/* ------------------------------------------------------------------ */
__global__ __launch_bounds__(256) void mlp01_kernel(
    const float* __restrict__ actions, const float* __restrict__ w0,
    const float* __restrict__ b0, const float* __restrict__ w1,
    const float* __restrict__ b1)
{
    __shared__ float a_s[64 * DA];        /* 8 KB  */
    __shared__ float h0T[HID * 68];       /* [feature][token], padded; 34.8 KB */

    const int tid = threadIdx.x;
    const int tok0 = blockIdx.x * 64;

    /* load actions tile (64 x 32 floats) as float4, coalesced */
#pragma unroll
    for (int p = 0; p < 2; p++) {
        int u = p * 256 + tid;            /* float4 unit, 512 total */
        int tok = u >> 3;
        int c = (u & 7) * 4;
        float4 v = *reinterpret_cast<const float4*>(
            &actions[(size_t)(tok0 + tok) * DA + c]);
        a_s[tok * DA + c + 0] = v.x;
        a_s[tok * DA + c + 1] = v.y;
        a_s[tok * DA + c + 2] = v.z;
        a_s[tok * DA + c + 3] = v.w;
    }
    __syncthreads();

    const int j  = tid & 127;   /* feature index */
    const int hi = tid >> 7;    /* token-half    */

    /* layer 0: cache this thread's w0 column in registers */
    float w0c[DA];
#pragma unroll
    for (int k = 0; k < DA; k++) w0c[k] = w0[k * HID + j];
    const float b0v = b0[j];

    for (int o = 0; o < 32; o++) {
        int tok = o * 2 + hi;
        float acc = b0v;
#pragma unroll
        for (int k = 0; k < DA; k++) acc += a_s[tok * DA + k] * w0c[k];
        h0T[j * 68 + tok] = fmaxf(acc, 0.f);
    }
    __syncthreads();

    /* layer 1: thread owns output feature j for 32 tokens */
    float accs[32];
#pragma unroll
    for (int m = 0; m < 32; m++) accs[m] = 0.f;
    const int m0 = hi * 32;

#pragma unroll 2
    for (int k = 0; k < HID; k++) {
        float wv = w1[k * HID + j];
        const float4* hp = reinterpret_cast<const float4*>(&h0T[k * 68 + m0]);
#pragma unroll
        for (int m4 = 0; m4 < 8; m4++) {
            float4 hv = hp[m4];
            accs[m4 * 4 + 0] += hv.x * wv;
            accs[m4 * 4 + 1] += hv.y * wv;
            accs[m4 * 4 + 2] += hv.z * wv;
            accs[m4 * 4 + 3] += hv.w * wv;
        }
    }
    const float b1v = b1[j];
#pragma unroll
    for (int m = 0; m < 32; m++) {
        g_h1[(size_t)(tok0 + m0 + m) * HID + j] = fmaxf(accs[m] + b1v, 0.f);
    }
}

/* ------------------------------------------------------------------ */
/* Kernel B: g_trans = g_h1 @ w2 + b2   (65536x128 @ 128x4096, fp32)   */
/* 128x128 tile / block, 256 threads, 8x8 thread tile via fma.rn.f32x2 */
/* ------------------------------------------------------------------ */
#define BM 128
#define BN 128
#define BKC 32

__device__ __forceinline__ unsigned long long pack2(float x)
{
    unsigned long long r;
    unsigned int xi = __float_as_uint(x);
    asm("mov.b64 %0, {%1, %1};" : "=l"(r) : "r"(xi));
    return r;
}
__device__ __forceinline__ void fma2(unsigned long long& d,
                                     unsigned long long a,
                                     unsigned long long b)
{
    asm("fma.rn.f32x2 %0, %1, %2, %0;" : "+l"(d) : "l"(a), "l"(b));
}
__device__ __forceinline__ void add2(unsigned long long& d, unsigned long long b)
{
    asm("add.rn.f32x2 %0, %0, %1;" : "+l"(d) : "l"(b));
}

__global__ __launch_bounds__(256, 2) void gemm_kernel(
    const float* __restrict__ w2, const float* __restrict__ b2)
{
    __shared__ float a_s[BM * (BKC + 1)]; /* 16896 B */
    __shared__ float b_s[BKC * BN];       /* 16384 B */

    const int tid = threadIdx.x;
    const int tx = tid & 15;
    const int ty = tid >> 4;
    const int n0 = blockIdx.x * BN;
    const size_t m0 = (size_t)blockIdx.y * BM;

    unsigned long long acc[8][4];
#pragma unroll
    for (int i = 0; i < 8; i++)
#pragma unroll
        for (int q = 0; q < 4; q++) acc[i][q] = 0ull;

    for (int kc = 0; kc < HID; kc += BKC) {
        __syncthreads();
        /* A tile: 128 rows x 32 cols */
        {
            int c = (tid & 7) * 4;
            int r0 = tid >> 3;
#pragma unroll
            for (int p = 0; p < 4; p++) {
                int row = r0 + p * 32;
                float4 v = *reinterpret_cast<const float4*>(
                    &g_h1[(m0 + row) * HID + kc + c]);
                float* d = &a_s[row * (BKC + 1) + c];
                d[0] = v.x; d[1] = v.y; d[2] = v.z; d[3] = v.w;
            }
        }
        /* B tile: 32 rows x 128 cols */
        {
            int cB = (tid & 31) * 4;
            int rB = tid >> 5;
#pragma unroll
            for (int p = 0; p < 4; p++) {
                int row = rB + p * 8;
                float4 v = *reinterpret_cast<const float4*>(
                    &w2[(size_t)(kc + row) * TRANS_N + n0 + cB]);
                *reinterpret_cast<float4*>(&b_s[row * BN + cB]) = v;
            }
        }
        __syncthreads();

#pragma unroll 4
        for (int k = 0; k < BKC; k++) {
            unsigned long long pa[8];
#pragma unroll
            for (int i = 0; i < 8; i++)
                pa[i] = pack2(a_s[(ty * 8 + i) * (BKC + 1) + k]);
            const ulonglong2* bp =
                reinterpret_cast<const ulonglong2*>(&b_s[k * BN + tx * 8]);
            ulonglong2 B0 = bp[0];
            ulonglong2 B1 = bp[1];
            unsigned long long bb[4] = { B0.x, B0.y, B1.x, B1.y };
#pragma unroll
            for (int i = 0; i < 8; i++)
#pragma unroll
                for (int q = 0; q < 4; q++) fma2(acc[i][q], pa[i], bb[q]);
        }
    }

    /* epilogue: + b2, store */
    const unsigned long long* b2p =
        reinterpret_cast<const unsigned long long*>(b2 + n0 + tx * 8);
    unsigned long long bv[4] = { b2p[0], b2p[1], b2p[2], b2p[3] };
#pragma unroll
    for (int i = 0; i < 8; i++) {
#pragma unroll
        for (int q = 0; q < 4; q++) add2(acc[i][q], bv[q]);
        float* crow = &g_trans[(m0 + ty * 8 + i) * TRANS_N + n0 + tx * 8];
        reinterpret_cast<ulonglong2*>(crow)[0] =
            make_ulonglong2(acc[i][0], acc[i][1]);
        reinterpret_cast<ulonglong2*>(crow)[1] =
            make_ulonglong2(acc[i][2], acc[i][3]);
    }
}

/* ------------------------------------------------------------------ */
/* Kernel C: sequential RNN scan. One block per batch, 128 threads.    */
/* 6-stage cp.async ring prefetches T (loads never depend on hidden).  */
/* ------------------------------------------------------------------ */
#define NSTAGE 6
#define STAGE_FLOATS TRANS_N  /* 4096 floats = 16 KB per stage */

__global__ __launch_bounds__(128) void scan_kernel(
    const float* __restrict__ init_hidden, float* __restrict__ out)
{
    extern __shared__ float Tbuf[];  /* NSTAGE * 16 KB */
    __shared__ float u_s[DS];
    __shared__ float p_s[2 * DS];
    __shared__ float wsum[2];

    const int tid = threadIdx.x;
    const int b = blockIdx.x;
    const int j = tid & 63;
    const int ic = tid >> 6;
    const int lane = tid & 31;
    const int wid = tid >> 5;
    const float* trans = g_trans + (size_t)b * SEQ * TRANS_N;

    const uint32_t Tsm = (uint32_t)__cvta_generic_to_shared(Tbuf);

    /* prologue: issue stages 0..NSTAGE-1 */
    for (int s = 0; s < NSTAGE; s++) {
        const float* src = trans + (size_t)s * TRANS_N;
        uint32_t dst = Tsm + (uint32_t)(s % NSTAGE) * STAGE_FLOATS * 4u;
#pragma unroll
        for (int q = 0; q < 8; q++) {
            int u = q * 128 + tid;
            asm volatile("cp.async.cg.shared.global [%0], [%1], 16;"
                         :: "r"(dst + (uint32_t)u * 16u), "l"(src + (size_t)u * 4));
        }
        asm volatile("cp.async.commit_group;");
    }

    /* h0 = l2norm(init_hidden), broadcast over batch */
    {
        float v = 0.f;
        if (tid < 64) {
            v = init_hidden[j];
            float s = v * v;
            s += __shfl_xor_sync(0xffffffffu, s, 16);
            s += __shfl_xor_sync(0xffffffffu, s, 8);
            s += __shfl_xor_sync(0xffffffffu, s, 4);
            s += __shfl_xor_sync(0xffffffffu, s, 2);
            s += __shfl_xor_sync(0xffffffffu, s, 1);
            if (lane == 0) wsum[wid] = s;
        }
        __syncthreads();
        float inv = 1.f / fmaxf(sqrtf(wsum[0] + wsum[1]), 1e-12f);
        if (tid < 64) u_s[j] = v * inv;
        __syncthreads();
    }

    for (int t = 0; t < SEQ; t++) {
        asm volatile("cp.async.wait_group %0;" :: "n"(NSTAGE - 1));
        __syncthreads();

        const float* T = Tbuf + (t % NSTAGE) * STAGE_FLOATS;
        float a0 = 0.f, a1 = 0.f, a2 = 0.f, a3 = 0.f;
        const int ib = ic * 32;
#pragma unroll
        for (int i = 0; i < 32; i += 4) {
            a0 += u_s[ib + i + 0] * T[(ib + i + 0) * 64 + j];
            a1 += u_s[ib + i + 1] * T[(ib + i + 1) * 64 + j];
            a2 += u_s[ib + i + 2] * T[(ib + i + 2) * 64 + j];
            a3 += u_s[ib + i + 3] * T[(ib + i + 3) * 64 + j];
        }
        p_s[ic * 64 + j] = (a0 + a1) + (a2 + a3);
        __syncthreads();

        float u = 0.f;
        if (tid < 64) {
            float z = p_s[j] + p_s[64 + j];
            u = fmaxf(z, 0.f);
            float s = u * u;
            s += __shfl_xor_sync(0xffffffffu, s, 16);
            s += __shfl_xor_sync(0xffffffffu, s, 8);
            s += __shfl_xor_sync(0xffffffffu, s, 4);
            s += __shfl_xor_sync(0xffffffffu, s, 2);
            s += __shfl_xor_sync(0xffffffffu, s, 1);
            if (lane == 0) wsum[wid] = s;
        }
        __syncthreads();
        float inv = 1.f / fmaxf(sqrtf(wsum[0] + wsum[1]), 1e-12f);
        if (tid < 64) {
            float h = u * inv;
            out[((size_t)b * SEQ + t) * DS + j] = h;
            u_s[j] = h;
        }
        __syncthreads();

        /* prefetch stage t+NSTAGE (buffer t%NSTAGE is now free) */
        int st = t + NSTAGE;
        if (st < SEQ) {
            const float* src = trans + (size_t)st * TRANS_N;
            uint32_t dst = Tsm + (uint32_t)(st % NSTAGE) * STAGE_FLOATS * 4u;
#pragma unroll
            for (int q = 0; q < 8; q++) {
                int u2 = q * 128 + tid;
                asm volatile("cp.async.cg.shared.global [%0], [%1], 16;"
                             :: "r"(dst + (uint32_t)u2 * 16u), "l"(src + (size_t)u2 * 4));
            }
        }
        asm volatile("cp.async.commit_group;");
    }
}

/* ------------------------------------------------------------------ */
extern "C" void kernel_launch(void* const* d_in, const int* in_sizes, int n_in,
                              void* d_out, int out_size)
{
    const float* actions = (const float*)d_in[0];
    const float* w0 = (const float*)d_in[1];
    const float* b0 = (const float*)d_in[2];
    const float* w1 = (const float*)d_in[3];
    const float* b1 = (const float*)d_in[4];
    const float* w2 = (const float*)d_in[5];
    const float* b2 = (const float*)d_in[6];
    const float* ih = (const float*)d_in[7];
    float* out = (float*)d_out;

    mlp01_kernel<<<NTOK / 64, 256>>>(actions, w0, b0, w1, b1);
    gemm_kernel<<<dim3(TRANS_N / BN, NTOK / BM), 256>>>(w2, b2);

    cudaFuncSetAttribute(scan_kernel,
                         cudaFuncAttributeMaxDynamicSharedMemorySize,
                         NSTAGE * STAGE_FLOATS * 4);
    scan_kernel<<<BATCH, 128, NSTAGE * STAGE_FLOATS * 4>>>(ih, out);
}

// round 6
// speedup vs baseline: 1.7508x; 1.7508x over previous
#include <cuda_runtime.h>
#include <cuda_bf16.h>
#include <cstdint>
#include <cstddef>

#define BATCH 32
#define SEQ 2048
#define DA 32
#define HID 128
#define DS 64
#define NTOK (BATCH * SEQ)       /* 65536 */
#define TRANS_N (DS * DS)        /* 4096  */

/* Scratch: __device__ globals (no allocation allowed). */
__device__ __nv_bfloat16 g_h1h[(size_t)NTOK * HID];     /* 16 MB */
__device__ __nv_bfloat16 g_h1l[(size_t)NTOK * HID];     /* 16 MB */
__device__ __nv_bfloat16 g_w2hT[(size_t)TRANS_N * HID]; /* 1 MB, [n][k] */
__device__ __nv_bfloat16 g_w2lT[(size_t)TRANS_N * HID]; /* 1 MB */
__device__ float g_trans[(size_t)NTOK * TRANS_N];       /* 1 GiB */

/* ------------------------------------------------------------------ */
/* Kernel A: h1 = relu(relu(a@w0+b0)@w1 + b1); emit bf16 hi/lo split.  */
/* ------------------------------------------------------------------ */
__global__ __launch_bounds__(256) void mlp01_kernel(
    const float* __restrict__ actions, const float* __restrict__ w0,
    const float* __restrict__ b0, const float* __restrict__ w1,
    const float* __restrict__ b1)
{
    __shared__ float a_s[64 * DA];
    __shared__ float h0T[HID * 68];

    const int tid = threadIdx.x;
    const int tok0 = blockIdx.x * 64;

#pragma unroll
    for (int p = 0; p < 2; p++) {
        int u = p * 256 + tid;
        int tok = u >> 3;
        int c = (u & 7) * 4;
        float4 v = *reinterpret_cast<const float4*>(
            &actions[(size_t)(tok0 + tok) * DA + c]);
        a_s[tok * DA + c + 0] = v.x;
        a_s[tok * DA + c + 1] = v.y;
        a_s[tok * DA + c + 2] = v.z;
        a_s[tok * DA + c + 3] = v.w;
    }
    __syncthreads();

    const int j  = tid & 127;
    const int hi = tid >> 7;

    float w0c[DA];
#pragma unroll
    for (int k = 0; k < DA; k++) w0c[k] = w0[k * HID + j];
    const float b0v = b0[j];

    for (int o = 0; o < 32; o++) {
        int tok = o * 2 + hi;
        float acc = b0v;
#pragma unroll
        for (int k = 0; k < DA; k++) acc += a_s[tok * DA + k] * w0c[k];
        h0T[j * 68 + tok] = fmaxf(acc, 0.f);
    }
    __syncthreads();

    float accs[32];
#pragma unroll
    for (int m = 0; m < 32; m++) accs[m] = 0.f;
    const int m0 = hi * 32;

#pragma unroll 2
    for (int k = 0; k < HID; k++) {
        float wv = w1[k * HID + j];
        const float4* hp = reinterpret_cast<const float4*>(&h0T[k * 68 + m0]);
#pragma unroll
        for (int m4 = 0; m4 < 8; m4++) {
            float4 hv = hp[m4];
            accs[m4 * 4 + 0] += hv.x * wv;
            accs[m4 * 4 + 1] += hv.y * wv;
            accs[m4 * 4 + 2] += hv.z * wv;
            accs[m4 * 4 + 3] += hv.w * wv;
        }
    }
    const float b1v = b1[j];
#pragma unroll
    for (int m = 0; m < 32; m++) {
        float h = fmaxf(accs[m] + b1v, 0.f);
        __nv_bfloat16 h_hi = __float2bfloat16(h);
        __nv_bfloat16 h_lo = __float2bfloat16(h - __bfloat162float(h_hi));
        size_t idx = (size_t)(tok0 + m0 + m) * HID + j;
        g_h1h[idx] = h_hi;
        g_h1l[idx] = h_lo;
    }
}

/* ------------------------------------------------------------------ */
/* Kernel A2: transpose+split w2 [128,4096] -> w2hT/w2lT [4096,128].   */
/* ------------------------------------------------------------------ */
__global__ __launch_bounds__(256) void convw2_kernel(const float* __restrict__ w2)
{
    __shared__ float tile[32][33];
    const int n0 = blockIdx.x * 32;
    const int k0 = blockIdx.y * 32;
    const int tx = threadIdx.x;          /* 0..31 */
    const int ty = threadIdx.y;          /* 0..7  */

#pragma unroll
    for (int p = 0; p < 4; p++)
        tile[ty + p * 8][tx] = w2[(size_t)(k0 + ty + p * 8) * TRANS_N + n0 + tx];
    __syncthreads();

#pragma unroll
    for (int p = 0; p < 4; p++) {
        float v = tile[tx][ty + p * 8];
        __nv_bfloat16 vh = __float2bfloat16(v);
        __nv_bfloat16 vl = __float2bfloat16(v - __bfloat162float(vh));
        size_t o = (size_t)(n0 + ty + p * 8) * HID + k0 + tx;
        g_w2hT[o] = vh;
        g_w2lT[o] = vl;
    }
}

/* ------------------------------------------------------------------ */
/* Kernel B: split-bf16 GEMM via mma.sync (HMMA).                      */
/* C[65536,4096] = AhBh + AhBl + AlBh + b2 (fp32 accum).               */
/* CTA tile 128x128, 8 warps (2x4), warp tile 64x32, m16n8k16.         */
/* Six K-chunks of 64 (3 term-pairs x 2 halves), 2-stage cp.async.     */
/* ------------------------------------------------------------------ */
#define CHUNK_UNITS 1024u            /* 128 rows x 8 units of 16B      */
#define CHUNK_BYTES 16384u
#define STAGE_BYTES (2u * CHUNK_BYTES)
#define GB_DSMEM (2u * STAGE_BYTES)  /* 64 KB */

static __device__ __forceinline__ void ldmx4(uint32_t& r0, uint32_t& r1,
                                             uint32_t& r2, uint32_t& r3,
                                             uint32_t addr)
{
    asm volatile("ldmatrix.sync.aligned.m8n8.x4.shared.b16 {%0,%1,%2,%3}, [%4];"
                 : "=r"(r0), "=r"(r1), "=r"(r2), "=r"(r3) : "r"(addr));
}

static __device__ __forceinline__ void mma16816(float* c, const uint32_t* a,
                                                const uint32_t* b)
{
    asm volatile(
        "mma.sync.aligned.m16n8k16.row.col.f32.bf16.bf16.f32 "
        "{%0,%1,%2,%3}, {%4,%5,%6,%7}, {%8,%9}, {%0,%1,%2,%3};"
        : "+f"(c[0]), "+f"(c[1]), "+f"(c[2]), "+f"(c[3])
        : "r"(a[0]), "r"(a[1]), "r"(a[2]), "r"(a[3]), "r"(b[0]), "r"(b[1]));
}

__global__ __launch_bounds__(256, 2) void gemm_mma_kernel(
    const float* __restrict__ b2)
{
    extern __shared__ __align__(128) char sm[];

    const int tid = threadIdx.x;
    const int wid = tid >> 5;
    const int lane = tid & 31;
    const size_t m0 = (size_t)blockIdx.y * 128;
    const int n0 = blockIdx.x * 128;

    const int m_w = (wid & 1) * 64;       /* warp m offset in tile */
    const int n_w = (wid >> 1) * 32;      /* warp n offset in tile */

    const uint32_t smb = (uint32_t)__cvta_generic_to_shared(sm);

    /* chunk c: 0:(Ah,Bh,k0) 1:(Ah,Bh,k64) 2:(Ah,Bl,k0) 3:(Ah,Bl,k64)
                4:(Al,Bh,k0) 5:(Al,Bh,k64)                             */
    auto load_chunk = [&](int c) {
        const __nv_bfloat16* ap = (c < 4) ? g_h1h : g_h1l;
        const __nv_bfloat16* bp = (c == 2 || c == 3) ? g_w2lT : g_w2hT;
        const int koff = (c & 1) * 64;
        const uint32_t Ab = smb + (uint32_t)(c & 1) * STAGE_BYTES;
        const uint32_t Bb = Ab + CHUNK_BYTES;
#pragma unroll
        for (int q = 0; q < 4; q++) {
            int u = q * 256 + tid;        /* 1024 16B units */
            int row = u >> 3;
            int col8 = u & 7;
            uint32_t dst = (uint32_t)((row * 8 + (col8 ^ (row & 7))) * 16);
            const char* srcA = (const char*)(ap + (m0 + row) * HID + koff) + col8 * 16;
            const char* srcB = (const char*)(bp + (size_t)(n0 + row) * HID + koff) + col8 * 16;
            asm volatile("cp.async.cg.shared.global [%0], [%1], 16;"
                         :: "r"(Ab + dst), "l"(srcA));
            asm volatile("cp.async.cg.shared.global [%0], [%1], 16;"
                         :: "r"(Bb + dst), "l"(srcB));
        }
        asm volatile("cp.async.commit_group;" ::: "memory");
    };

    float acc[4][4][4];
#pragma unroll
    for (int i = 0; i < 4; i++)
#pragma unroll
        for (int j = 0; j < 4; j++)
#pragma unroll
            for (int q = 0; q < 4; q++) acc[i][j][q] = 0.f;

    /* precomputed ldmatrix row/kunit-lane mapping */
    const int a_row = lane & 15;                         /* within m16 tile  */
    const int a_ksel = lane >> 4;                        /* 0/1 -> k0/k8     */
    const int b_row = (lane & 7) | ((lane & 16) >> 1);   /* within n16 pair  */
    const int b_ksel = (lane >> 3) & 1;

    load_chunk(0);

    for (int c = 0; c < 6; c++) {
        if (c < 5) load_chunk(c + 1);
        if (c < 5) asm volatile("cp.async.wait_group 1;" ::: "memory");
        else       asm volatile("cp.async.wait_group 0;" ::: "memory");
        __syncthreads();

        const uint32_t Ab = smb + (uint32_t)(c & 1) * STAGE_BYTES;
        const uint32_t Bb = Ab + CHUNK_BYTES;

#pragma unroll
        for (int k16 = 0; k16 < 4; k16++) {
            uint32_t afr[4][4];
            uint32_t bfr[4][2];
#pragma unroll
            for (int mi = 0; mi < 4; mi++) {
                int row = m_w + mi * 16 + a_row;
                int ku = (k16 * 2 + a_ksel) ^ (row & 7);
                ldmx4(afr[mi][0], afr[mi][1], afr[mi][2], afr[mi][3],
                      Ab + (uint32_t)((row * 8 + ku) * 16));
            }
#pragma unroll
            for (int np = 0; np < 2; np++) {
                int row = n_w + np * 16 + b_row;
                int ku = (k16 * 2 + b_ksel) ^ (row & 7);
                uint32_t r0, r1, r2, r3;
                ldmx4(r0, r1, r2, r3, Bb + (uint32_t)((row * 8 + ku) * 16));
                bfr[np * 2 + 0][0] = r0; bfr[np * 2 + 0][1] = r1;
                bfr[np * 2 + 1][0] = r2; bfr[np * 2 + 1][1] = r3;
            }
#pragma unroll
            for (int mi = 0; mi < 4; mi++)
#pragma unroll
                for (int ni = 0; ni < 4; ni++)
                    mma16816(acc[mi][ni], afr[mi], bfr[ni]);
        }
        __syncthreads();
    }

    /* epilogue: bias + direct float2 stores */
    float2 bias[4];
#pragma unroll
    for (int ni = 0; ni < 4; ni++) {
        int col = n0 + n_w + ni * 8 + (lane & 3) * 2;
        bias[ni] = *reinterpret_cast<const float2*>(&b2[col]);
    }
#pragma unroll
    for (int mi = 0; mi < 4; mi++) {
        size_t r0 = m0 + m_w + mi * 16 + (lane >> 2);
#pragma unroll
        for (int ni = 0; ni < 4; ni++) {
            int col = n0 + n_w + ni * 8 + (lane & 3) * 2;
            float2 v0 = make_float2(acc[mi][ni][0] + bias[ni].x,
                                    acc[mi][ni][1] + bias[ni].y);
            float2 v1 = make_float2(acc[mi][ni][2] + bias[ni].x,
                                    acc[mi][ni][3] + bias[ni].y);
            *reinterpret_cast<float2*>(&g_trans[r0 * TRANS_N + col]) = v0;
            *reinterpret_cast<float2*>(&g_trans[(r0 + 8) * TRANS_N + col]) = v1;
        }
    }
}

/* ------------------------------------------------------------------ */
/* Kernel C: sequential RNN scan (unchanged).                          */
/* ------------------------------------------------------------------ */
#define NSTAGE 6
#define STAGE_FLOATS TRANS_N

__global__ __launch_bounds__(128) void scan_kernel(
    const float* __restrict__ init_hidden, float* __restrict__ out)
{
    extern __shared__ float Tbuf[];
    __shared__ float u_s[DS];
    __shared__ float p_s[2 * DS];
    __shared__ float wsum[2];

    const int tid = threadIdx.x;
    const int b = blockIdx.x;
    const int j = tid & 63;
    const int ic = tid >> 6;
    const int lane = tid & 31;
    const int wid = tid >> 5;
    const float* trans = g_trans + (size_t)b * SEQ * TRANS_N;

    const uint32_t Tsm = (uint32_t)__cvta_generic_to_shared(Tbuf);

    for (int s = 0; s < NSTAGE; s++) {
        const float* src = trans + (size_t)s * TRANS_N;
        uint32_t dst = Tsm + (uint32_t)(s % NSTAGE) * STAGE_FLOATS * 4u;
#pragma unroll
        for (int q = 0; q < 8; q++) {
            int u = q * 128 + tid;
            asm volatile("cp.async.cg.shared.global [%0], [%1], 16;"
                         :: "r"(dst + (uint32_t)u * 16u), "l"(src + (size_t)u * 4));
        }
        asm volatile("cp.async.commit_group;");
    }

    {
        float v = 0.f;
        if (tid < 64) {
            v = init_hidden[j];
            float s = v * v;
            s += __shfl_xor_sync(0xffffffffu, s, 16);
            s += __shfl_xor_sync(0xffffffffu, s, 8);
            s += __shfl_xor_sync(0xffffffffu, s, 4);
            s += __shfl_xor_sync(0xffffffffu, s, 2);
            s += __shfl_xor_sync(0xffffffffu, s, 1);
            if (lane == 0) wsum[wid] = s;
        }
        __syncthreads();
        float inv = 1.f / fmaxf(sqrtf(wsum[0] + wsum[1]), 1e-12f);
        if (tid < 64) u_s[j] = v * inv;
        __syncthreads();
    }

    for (int t = 0; t < SEQ; t++) {
        asm volatile("cp.async.wait_group %0;" :: "n"(NSTAGE - 1));
        __syncthreads();

        const float* T = Tbuf + (t % NSTAGE) * STAGE_FLOATS;
        float a0 = 0.f, a1 = 0.f, a2 = 0.f, a3 = 0.f;
        const int ib = ic * 32;
#pragma unroll
        for (int i = 0; i < 32; i += 4) {
            a0 += u_s[ib + i + 0] * T[(ib + i + 0) * 64 + j];
            a1 += u_s[ib + i + 1] * T[(ib + i + 1) * 64 + j];
            a2 += u_s[ib + i + 2] * T[(ib + i + 2) * 64 + j];
            a3 += u_s[ib + i + 3] * T[(ib + i + 3) * 64 + j];
        }
        p_s[ic * 64 + j] = (a0 + a1) + (a2 + a3);
        __syncthreads();

        float u = 0.f;
        if (tid < 64) {
            float z = p_s[j] + p_s[64 + j];
            u = fmaxf(z, 0.f);
            float s = u * u;
            s += __shfl_xor_sync(0xffffffffu, s, 16);
            s += __shfl_xor_sync(0xffffffffu, s, 8);
            s += __shfl_xor_sync(0xffffffffu, s, 4);
            s += __shfl_xor_sync(0xffffffffu, s, 2);
            s += __shfl_xor_sync(0xffffffffu, s, 1);
            if (lane == 0) wsum[wid] = s;
        }
        __syncthreads();
        float inv = 1.f / fmaxf(sqrtf(wsum[0] + wsum[1]), 1e-12f);
        if (tid < 64) {
            float h = u * inv;
            out[((size_t)b * SEQ + t) * DS + j] = h;
            u_s[j] = h;
        }
        __syncthreads();

        int st = t + NSTAGE;
        if (st < SEQ) {
            const float* src = trans + (size_t)st * TRANS_N;
            uint32_t dst = Tsm + (uint32_t)(st % NSTAGE) * STAGE_FLOATS * 4u;
#pragma unroll
            for (int q = 0; q < 8; q++) {
                int u2 = q * 128 + tid;
                asm volatile("cp.async.cg.shared.global [%0], [%1], 16;"
                             :: "r"(dst + (uint32_t)u2 * 16u), "l"(src + (size_t)u2 * 4));
            }
        }
        asm volatile("cp.async.commit_group;");
    }
}

/* ------------------------------------------------------------------ */
extern "C" void kernel_launch(void* const* d_in, const int* in_sizes, int n_in,
                              void* d_out, int out_size)
{
    const float* actions = (const float*)d_in[0];
    const float* w0 = (const float*)d_in[1];
    const float* b0 = (const float*)d_in[2];
    const float* w1 = (const float*)d_in[3];
    const float* b1 = (const float*)d_in[4];
    const float* w2 = (const float*)d_in[5];
    const float* b2 = (const float*)d_in[6];
    const float* ih = (const float*)d_in[7];
    float* out = (float*)d_out;

    mlp01_kernel<<<NTOK / 64, 256>>>(actions, w0, b0, w1, b1);
    convw2_kernel<<<dim3(TRANS_N / 32, HID / 32), dim3(32, 8)>>>(w2);

    cudaFuncSetAttribute(gemm_mma_kernel,
                         cudaFuncAttributeMaxDynamicSharedMemorySize, GB_DSMEM);
    gemm_mma_kernel<<<dim3(TRANS_N / 128, NTOK / 128), 256, GB_DSMEM>>>(b2);

    cudaFuncSetAttribute(scan_kernel,
                         cudaFuncAttributeMaxDynamicSharedMemorySize,
                         NSTAGE * STAGE_FLOATS * 4);
    scan_kernel<<<BATCH, 128, NSTAGE * STAGE_FLOATS * 4>>>(ih, out);
}